// round 16
// baseline (speedup 1.0000x reference)
#include <cuda_runtime.h>
#include <cuda_bf16.h>

// Problem constants (fixed by dataset)
#define B_DIM 64
#define L_DIM 512
#define ROWS_PER_BLOCK 8       // 8 warps, 1 row each per tile
#define RB_COUNT (L_DIM / ROWS_PER_BLOCK)   // 64 row-blocks per sample
#define TILES (B_DIM * RB_COUNT)            // 4096 tiles
#define NBLOCKS 1024           // single wave: <=1184 slots @ 32 regs
#define TILES_PER_BLOCK (TILES / NBLOCKS)   // 4

// Per-tile partial sums: [TILES][3]  (S1, S2, S3)
__device__ float g_partials[TILES * 3];
// Completion counter (self-resetting across graph replays)
__device__ int g_count;

// softplus core: log1p(exp(-|x|)) via fast MUFU ops (EX2 + LG2)
__device__ __forceinline__ float sp_core(float x) {
    return __logf(1.0f + __expf(-fabsf(x)));
}

// Release-ordered fetch-add: orders this thread's prior stores at gpu scope.
__device__ __forceinline__ int atomic_add_release(int* p, int v) {
    int old;
    asm volatile("atom.release.gpu.global.add.s32 %0, [%1], %2;"
                 : "=r"(old) : "l"(p), "r"(v) : "memory");
    return old;
}

__global__ __launch_bounds__(256) void fused_kernel(
    const float* __restrict__ inputs,
    const float* __restrict__ targets,
    const int*   __restrict__ seq_lens,
    float*       __restrict__ out)
{
    const int p    = blockIdx.x;
    const int w    = threadIdx.x >> 5;    // warp id = row within tile stripe
    const int lane = threadIdx.x & 31;

    __shared__ float red[3][ROWS_PER_BLOCK];
    __shared__ bool  is_last;

    // ── Persistent loop over 4 statically-assigned tiles ──
    // tile = p + i*1024  →  sample b = tile>>6 = p>>6 + 16*i (stratified),
    //                       row-block rb = tile & 63 (same rb all 4 tiles).
    #pragma unroll
    for (int i = 0; i < TILES_PER_BLOCK; i++) {
        const int tile = p + (i << 10);
        const int b    = tile >> 6;
        const int rb   = tile & (RB_COUNT - 1);

        const int sl  = seq_lens[b];
        const int row = rb * ROWS_PER_BLOCK + w;

        float s1 = 0.0f, s2 = 0.0f, s3 = 0.0f;

        if (row < sl) {
            const size_t base = ((size_t)b * L_DIM + row) * L_DIM;
            const float4* __restrict__ ip = (const float4*)(inputs  + base);
            const float4* __restrict__ tp = (const float4*)(targets + base);

            #pragma unroll
            for (int k = 0; k < L_DIM / 128; k++) {
                const int c = k * 128 + lane * 4;
                if (c < sl) {
                    const float4 x4 = ip[c >> 2];
                    const float4 t4 = tp[c >> 2];
                    const float xs[4] = {x4.x, x4.y, x4.z, x4.w};
                    const float ts[4] = {t4.x, t4.y, t4.z, t4.w};
                    #pragma unroll
                    for (int q = 0; q < 4; q++) {
                        if (c + q < sl) {
                            const float x = xs[q];
                            const float t = ts[q];
                            const float core = sp_core(x);
                            const float sp_neg = core + fmaxf(-x, 0.0f); // softplus(-x)
                            const float sp_pos = core + fmaxf( x, 0.0f); // softplus(x)
                            s1 += t;
                            s2 = fmaf(t, sp_neg, s2);
                            s3 = fmaf(1.0f - t, sp_pos, s3);
                        }
                    }
                }
            }
        }

        // warp reduce
        #pragma unroll
        for (int o = 16; o > 0; o >>= 1) {
            s1 += __shfl_xor_sync(0xFFFFFFFFu, s1, o);
            s2 += __shfl_xor_sync(0xFFFFFFFFu, s2, o);
            s3 += __shfl_xor_sync(0xFFFFFFFFu, s3, o);
        }

        if (lane == 0) { red[0][w] = s1; red[1][w] = s2; red[2][w] = s3; }
        __syncthreads();

        if (threadIdx.x == 0) {
            float a0 = 0.0f, a1 = 0.0f, a2 = 0.0f;
            #pragma unroll
            for (int r = 0; r < ROWS_PER_BLOCK; r++) {
                a0 += red[0][r]; a1 += red[1][r]; a2 += red[2][r];
            }
            g_partials[tile * 3 + 0] = a0;
            g_partials[tile * 3 + 1] = a1;
            g_partials[tile * 3 + 2] = a2;
        }
        __syncthreads();   // protect red[] before next tile overwrites it
    }

    // ── End-of-block signal: one atomic per block, all 1024 overlap at tail ──
    if (threadIdx.x == 0) {
        const int old = atomic_add_release(&g_count, 1);
        is_last = (old == NBLOCKS - 1);
    }
    __syncthreads();

    // ── Fused finalize: the last-arriving block (never waits for anyone) ──
    if (is_last) {
        __threadfence();  // acquire: one flush total, in this block only

        const int tid = threadIdx.x;
        const int fb  = tid >> 2;     // 0..63  sample
        const int sub = tid & 3;      // 0..3   lane within sample group

        float t1 = 0.0f, t2 = 0.0f, t3 = 0.0f;
        #pragma unroll
        for (int i = 0; i < RB_COUNT / 4; i++) {
            const int idx = (fb * RB_COUNT + (sub + i * 4)) * 3;
            t1 += g_partials[idx + 0];
            t2 += g_partials[idx + 1];
            t3 += g_partials[idx + 2];
        }

        #pragma unroll
        for (int o = 2; o > 0; o >>= 1) {
            t1 += __shfl_xor_sync(0xFFFFFFFFu, t1, o);
            t2 += __shfl_xor_sync(0xFFFFFFFFu, t2, o);
            t3 += __shfl_xor_sync(0xFFFFFFFFu, t3, o);
        }

        __shared__ float sh[B_DIM];
        if (sub == 0) {
            const float sl_f  = (float)seq_lens[fb];
            const float total = sl_f * sl_f;
            const float tmax  = fmaxf(total, 1.0f);
            const float density = (total > 0.0f) ? (t1 / tmax) : 0.0f;
            float wgt = 0.01f / (density + 1e-6f);
            wgt = fminf(fmaxf(wgt, 1.0f), 50.0f);
            sh[fb] = (wgt * t2 + t3) / tmax;
        }
        __syncthreads();

        if (tid < 32) {
            float v = sh[tid] + sh[tid + 32];
            #pragma unroll
            for (int o = 16; o > 0; o >>= 1)
                v += __shfl_xor_sync(0xFFFFFFFFu, v, o);
            if (tid == 0) {
                out[0] = v / (float)B_DIM;
                g_count = 0;   // reset for next graph replay
            }
        }
    }
}

extern "C" void kernel_launch(void* const* d_in, const int* in_sizes, int n_in,
                              void* d_out, int out_size)
{
    const float* inputs   = (const float*)d_in[0];
    const float* targets  = (const float*)d_in[1];
    const int*   seq_lens = (const int*)d_in[2];
    float*       out      = (float*)d_out;

    fused_kernel<<<NBLOCKS, 256>>>(inputs, targets, seq_lens, out);
}

// round 17
// speedup vs baseline: 1.0535x; 1.0535x over previous
#include <cuda_runtime.h>
#include <cuda_bf16.h>

// Problem constants (fixed by dataset)
#define B_DIM 64
#define L_DIM 512
#define NBLOCKS 1024            // 16 blocks per sample
#define BLOCKS_PER_SAMPLE 16
#define ROWS_PER_WARP 4         // each block covers 32 rows striped over 0..511

// Per-BLOCK partial sums: [NBLOCKS][3]  (S1, S2, S3) = 12 KB
__device__ float g_partials[NBLOCKS * 3];

// softplus core: log1p(exp(-|x|)) via fast MUFU ops (EX2 + LG2)
__device__ __forceinline__ float sp_core(float x) {
    return __logf(1.0f + __expf(-fabsf(x)));
}

// Unmasked accumulate of 4 elements (full in-bounds chunk)
__device__ __forceinline__ void accum4(const float4& x4, const float4& t4,
                                       float& s1, float& s2, float& s3) {
    const float xs[4] = {x4.x, x4.y, x4.z, x4.w};
    const float ts[4] = {t4.x, t4.y, t4.z, t4.w};
    #pragma unroll
    for (int q = 0; q < 4; q++) {
        const float x = xs[q];
        const float t = ts[q];
        const float core = sp_core(x);
        s1 += t;
        s2 = fmaf(t, core + fmaxf(-x, 0.0f), s2);          // t * softplus(-x)
        s3 = fmaf(1.0f - t, core + fmaxf(x, 0.0f), s3);    // (1-t) * softplus(x)
    }
}

__global__ __launch_bounds__(256) void partial_kernel(
    const float* __restrict__ inputs,
    const float* __restrict__ targets,
    const int*   __restrict__ seq_lens)
{
    const int p    = blockIdx.x;          // 0..1023
    const int b    = p & (B_DIM - 1);     // sample
    const int jj   = p >> 6;              // 0..15 row-stripe offset
    const int w    = threadIdx.x >> 5;
    const int lane = threadIdx.x & 31;

    const int sl  = seq_lens[b];
    const int nk  = sl >> 7;              // full 128-col chunks
    const int rem = sl & 127;
    const size_t sbase = (size_t)b * (L_DIM * L_DIM);

    float s1 = 0.0f, s2 = 0.0f, s3 = 0.0f;

    // Rows for this warp: jj + 16*(w + 8*i), i = 0..3 — striped over 0..511,
    // monotone in i so we can break on the first out-of-range row.
    #pragma unroll
    for (int i = 0; i < ROWS_PER_WARP; i++) {
        const int row = jj + 16 * w + 128 * i;
        if (row >= sl) break;

        const float4* __restrict__ ip =
            (const float4*)(inputs  + sbase + (size_t)row * L_DIM) + lane;
        const float4* __restrict__ tp =
            (const float4*)(targets + sbase + (size_t)row * L_DIM) + lane;

        // ── Full chunks: branchless, guard-free, prefetch next chunk ──
        if (nk > 0) {
            float4 x = ip[0];
            float4 t = tp[0];
            for (int k = 1; k < nk; k++) {
                const float4 xn = ip[k * 32];   // prefetch before processing
                const float4 tn = tp[k * 32];
                accum4(x, t, s1, s2, s3);
                x = xn; t = tn;
            }
            accum4(x, t, s1, s2, s3);
        }

        // ── Tail chunk: per-element guards only here ──
        if (rem) {
            const int c = nk * 128 + lane * 4;
            if (c < sl) {
                const float4 x4 = ip[nk * 32];
                const float4 t4 = tp[nk * 32];
                const float xs[4] = {x4.x, x4.y, x4.z, x4.w};
                const float ts[4] = {t4.x, t4.y, t4.z, t4.w};
                #pragma unroll
                for (int q = 0; q < 4; q++) {
                    if (c + q < sl) {
                        const float x = xs[q];
                        const float t = ts[q];
                        const float core = sp_core(x);
                        s1 += t;
                        s2 = fmaf(t, core + fmaxf(-x, 0.0f), s2);
                        s3 = fmaf(1.0f - t, core + fmaxf(x, 0.0f), s3);
                    }
                }
            }
        }
    }

    // warp reduce
    #pragma unroll
    for (int o = 16; o > 0; o >>= 1) {
        s1 += __shfl_xor_sync(0xFFFFFFFFu, s1, o);
        s2 += __shfl_xor_sync(0xFFFFFFFFu, s2, o);
        s3 += __shfl_xor_sync(0xFFFFFFFFu, s3, o);
    }

    // block reduce (all warps share sample b) → one triple per block
    __shared__ float red[3][8];
    if (lane == 0) { red[0][w] = s1; red[1][w] = s2; red[2][w] = s3; }
    __syncthreads();

    if (threadIdx.x == 0) {
        float a0 = 0.0f, a1 = 0.0f, a2 = 0.0f;
        #pragma unroll
        for (int r = 0; r < 8; r++) {
            a0 += red[0][r]; a1 += red[1][r]; a2 += red[2][r];
        }
        g_partials[p * 3 + 0] = a0;
        g_partials[p * 3 + 1] = a1;
        g_partials[p * 3 + 2] = a2;
    }
}

// Finalize: 1024 threads = 64 samples x 16 blocks-per-sample; one triple each.
__global__ __launch_bounds__(1024) void finalize_kernel(
    const int* __restrict__ seq_lens,
    float* __restrict__ out)
{
    const int tid = threadIdx.x;
    const int b   = tid >> 4;     // 0..63  sample
    const int sub = tid & 15;     // 0..15  block index within sample

    const int p = b + (sub << 6); // block id that produced this triple
    float s1 = g_partials[p * 3 + 0];
    float s2 = g_partials[p * 3 + 1];
    float s3 = g_partials[p * 3 + 2];

    // reduce within the 16-lane subgroup
    #pragma unroll
    for (int o = 8; o > 0; o >>= 1) {
        s1 += __shfl_xor_sync(0xFFFFFFFFu, s1, o);
        s2 += __shfl_xor_sync(0xFFFFFFFFu, s2, o);
        s3 += __shfl_xor_sync(0xFFFFFFFFu, s3, o);
    }

    __shared__ float sh[B_DIM];
    if (sub == 0) {
        const float sl_f  = (float)seq_lens[b];
        const float total = sl_f * sl_f;
        const float tmax  = fmaxf(total, 1.0f);
        const float density = (total > 0.0f) ? (s1 / tmax) : 0.0f;
        float wgt = 0.01f / (density + 1e-6f);
        wgt = fminf(fmaxf(wgt, 1.0f), 50.0f);
        sh[b] = (wgt * s2 + s3) / tmax;
    }
    __syncthreads();

    if (tid < 32) {
        float v = sh[tid] + sh[tid + 32];
        #pragma unroll
        for (int o = 16; o > 0; o >>= 1)
            v += __shfl_xor_sync(0xFFFFFFFFu, v, o);
        if (tid == 0) out[0] = v / (float)B_DIM;
    }
}

extern "C" void kernel_launch(void* const* d_in, const int* in_sizes, int n_in,
                              void* d_out, int out_size)
{
    const float* inputs   = (const float*)d_in[0];
    const float* targets  = (const float*)d_in[1];
    const int*   seq_lens = (const int*)d_in[2];
    float*       out      = (float*)d_out;

    partial_kernel<<<NBLOCKS, 256>>>(inputs, targets, seq_lens);
    finalize_kernel<<<1, 1024>>>(seq_lens, out);
}